// round 1
// baseline (speedup 1.0000x reference)
#include <cuda_runtime.h>
#include <math.h>

#define NC 200000
#define NF 64
#define NH 128
#define NS 512

// ---- scratch (static __device__ globals; no allocation allowed) ----
__device__ float    d_logits[NC];
__device__ float    d_e[NC];
__device__ float    d_w2k[NH];
__device__ float    d_c2;
__device__ unsigned d_gmax_u;
__device__ int      d_pcount;
__device__ int      d_pidx[NC];
__device__ float    d_pval[NC];
__device__ float    d_sums[NS];
__device__ float    d_sl[NS];
__device__ int      d_cnt[NS];

// order-preserving float<->uint mapping for atomicMax on floats
__device__ __forceinline__ unsigned ford(float f) {
    unsigned u = __float_as_uint(f);
    return (u & 0x80000000u) ? ~u : (u | 0x80000000u);
}
__device__ __forceinline__ float funord(unsigned u) {
    return __uint_as_float((u & 0x80000000u) ? (u ^ 0x80000000u) : ~u);
}

// ---- reset per-call state (kernel_launch must be replay-deterministic) ----
__global__ void k_init() {
    int t = blockIdx.x * blockDim.x + threadIdx.x;
    if (t < NS) d_sums[t] = 0.f;
    if (t == 0) { d_gmax_u = 0u; d_pcount = 0; }
}

// ---- fold W2/key_w into w2k[h] = sum_j W2[h][j]*kw[j]; c2 = b2 . kw ----
__global__ void k_prep(const float* __restrict__ W2, const float* __restrict__ b2,
                       const float* __restrict__ kw) {
    __shared__ float kws[NH];
    __shared__ float red[4];
    int h = threadIdx.x;  // 128 threads
    kws[h] = kw[h];
    __syncthreads();
    float s = 0.f;
#pragma unroll 8
    for (int j = 0; j < NH; j++) s += W2[h * NH + j] * kws[j];
    d_w2k[h] = s;
    float c = b2[h] * kws[h];
    for (int o = 16; o; o >>= 1) c += __shfl_xor_sync(0xffffffffu, c, o);
    if ((h & 31) == 0) red[h >> 5] = c;
    __syncthreads();
    if (h == 0) d_c2 = red[0] + red[1] + red[2] + red[3];
}

// ---- fused MLP: logits[c] = relu(x_c @ W1 + b1) . w2k + c2 ----
// 128 threads/block, 1 clause per thread, x in registers, W1 staged in smem
// (broadcast float4 reads, conflict-free).
__global__ void __launch_bounds__(128) k_mlp(const float* __restrict__ feat,
                                             const float* __restrict__ W1,
                                             const float* __restrict__ b1) {
    __shared__ float W1s[NF * NH];  // 32 KB
    int tid = threadIdx.x;
    for (int i = tid; i < NF * NH; i += 128) W1s[i] = W1[i];
    __syncthreads();

    int c = blockIdx.x * 128 + tid;
    if (c >= NC) return;

    float x[NF];
    const float4* fr = (const float4*)(feat + (size_t)c * NF);
#pragma unroll
    for (int i = 0; i < NF / 4; i++) {
        float4 v = fr[i];
        x[4 * i + 0] = v.x; x[4 * i + 1] = v.y;
        x[4 * i + 2] = v.z; x[4 * i + 3] = v.w;
    }

    float logit = d_c2;
    for (int h = 0; h < NH; h += 4) {
        float4 bb = *(const float4*)(b1 + h);
        float a0 = bb.x, a1 = bb.y, a2 = bb.z, a3 = bb.w;
#pragma unroll
        for (int k = 0; k < NF; k++) {
            float4 w = *(const float4*)&W1s[k * NH + h];
            float xv = x[k];
            a0 = fmaf(xv, w.x, a0);
            a1 = fmaf(xv, w.y, a1);
            a2 = fmaf(xv, w.z, a2);
            a3 = fmaf(xv, w.w, a3);
        }
        float4 wk = *(const float4*)&d_w2k[h];
        logit += fmaxf(a0, 0.f) * wk.x + fmaxf(a1, 0.f) * wk.y +
                 fmaxf(a2, 0.f) * wk.z + fmaxf(a3, 0.f) * wk.w;
    }
    d_logits[c] = logit;
}

// ---- global max of logits ----
__global__ void k_max() {
    int t = blockIdx.x * blockDim.x + threadIdx.x;
    float m = -3.4e38f;
    for (int n = t; n < NC; n += gridDim.x * blockDim.x) m = fmaxf(m, d_logits[n]);
    for (int o = 16; o; o >>= 1) m = fmaxf(m, __shfl_xor_sync(0xffffffffu, m, o));
    if ((threadIdx.x & 31) == 0) atomicMax(&d_gmax_u, ford(m));
}

// ---- e[n] = exp(logits[n]-gmax); compact proof indices ----
__global__ void k_exp(const int* __restrict__ proof) {
    float gmax = funord(d_gmax_u);
    int t = blockIdx.x * blockDim.x + threadIdx.x;
    for (int n = t; n < NC; n += gridDim.x * blockDim.x) {
        float l = d_logits[n];
        d_e[n] = expf(l - gmax);
        if (proof[n]) {
            int p = atomicAdd(&d_pcount, 1);
            d_pidx[p] = n;
            d_pval[p] = l;
        }
    }
}

// ---- denominator: sums[s] += sum_{n in chunk} sel[s][n]*e[n] ----
#define CHUNK 2048
#define DTPB 256
#define SPG 64
__global__ void __launch_bounds__(DTPB) k_denom(const int* __restrict__ sel) {
    __shared__ float es[CHUNK];
    __shared__ float red[DTPB / 32];
    int tid = threadIdx.x;
    int base = blockIdx.x * CHUNK;
    for (int i = tid; i < CHUNK; i += DTPB) {
        int n = base + i;
        es[i] = (n < NC) ? d_e[n] : 0.f;
    }
    __syncthreads();

    int s0 = blockIdx.y * SPG;
    int off = tid * 8;
    bool fast = (base + off + 8) <= NC;

    for (int s = s0; s < s0 + SPG; s++) {
        const int* mrow = sel + (size_t)s * NC + base;
        float acc = 0.f;
        if (fast) {
            int4 m0 = *(const int4*)(mrow + off);
            int4 m1 = *(const int4*)(mrow + off + 4);
            float4 e0 = *(const float4*)&es[off];
            float4 e1 = *(const float4*)&es[off + 4];
            if (m0.x) acc += e0.x;
            if (m0.y) acc += e0.y;
            if (m0.z) acc += e0.z;
            if (m0.w) acc += e0.w;
            if (m1.x) acc += e1.x;
            if (m1.y) acc += e1.y;
            if (m1.z) acc += e1.z;
            if (m1.w) acc += e1.w;
        } else {
            for (int j = 0; j < 8; j++) {
                int n = base + off + j;
                if (n < NC && mrow[off + j]) acc += es[off + j];
            }
        }
        for (int o = 16; o; o >>= 1) acc += __shfl_xor_sync(0xffffffffu, acc, o);
        if ((tid & 31) == 0) red[tid >> 5] = acc;
        __syncthreads();
        if (tid == 0) {
            float tot = 0.f;
#pragma unroll
            for (int w = 0; w < DTPB / 32; w++) tot += red[w];
            atomicAdd(&d_sums[s], tot);
        }
        __syncthreads();
    }
}

// ---- numerator: per step, gather over compacted proof set ----
__global__ void k_numer(const int* __restrict__ sel) {
    int s = blockIdx.x;
    int tid = threadIdx.x;  // 256
    int P = d_pcount;
    float sl = 0.f;
    int cnt = 0;
    const int* srow = sel + (size_t)s * NC;
    for (int j = tid; j < P; j += 256) {
        int n = d_pidx[j];
        if (srow[n]) { sl += d_pval[j]; cnt++; }
    }
    for (int o = 16; o; o >>= 1) {
        sl += __shfl_xor_sync(0xffffffffu, sl, o);
        cnt += __shfl_xor_sync(0xffffffffu, cnt, o);
    }
    __shared__ float rs[8];
    __shared__ int rc[8];
    if ((tid & 31) == 0) { rs[tid >> 5] = sl; rc[tid >> 5] = cnt; }
    __syncthreads();
    if (tid == 0) {
        float ts = 0.f;
        int tc = 0;
#pragma unroll
        for (int w = 0; w < 8; w++) { ts += rs[w]; tc += rc[w]; }
        d_sl[s] = ts;
        d_cnt[s] = tc;
    }
}

// ---- loss = mean_s( gmax + log(sums[s]) - sl[s]/cnt[s] ) ----
__global__ void k_final(float* out) {
    float gmax = funord(d_gmax_u);
    int t = threadIdx.x;  // 512
    float v = (gmax + logf(d_sums[t])) - d_sl[t] / (float)d_cnt[t];
    for (int o = 16; o; o >>= 1) v += __shfl_xor_sync(0xffffffffu, v, o);
    __shared__ float red[16];
    if ((t & 31) == 0) red[t >> 5] = v;
    __syncthreads();
    if (t == 0) {
        float tot = 0.f;
#pragma unroll
        for (int w = 0; w < 16; w++) tot += red[w];
        out[0] = tot / (float)NS;
    }
}

extern "C" void kernel_launch(void* const* d_in, const int* in_sizes, int n_in,
                              void* d_out, int out_size) {
    const float* feat = (const float*)d_in[0];
    const float* W1   = (const float*)d_in[1];
    const float* b1   = (const float*)d_in[2];
    const float* W2   = (const float*)d_in[3];
    const float* b2   = (const float*)d_in[4];
    const float* kw   = (const float*)d_in[5];
    const int*   sel  = (const int*)d_in[6];
    const int*   proof= (const int*)d_in[7];
    float* out = (float*)d_out;

    k_init<<<1, 512>>>();
    k_prep<<<1, 128>>>(W2, b2, kw);
    k_mlp<<<(NC + 127) / 128, 128>>>(feat, W1, b1);
    k_max<<<200, 256>>>();
    k_exp<<<200, 256>>>(proof);
    dim3 dg((NC + CHUNK - 1) / CHUNK, NS / SPG);
    k_denom<<<dg, DTPB>>>(sel);
    k_numer<<<NS, 256>>>(sel);
    k_final<<<1, NS>>>(out);
}

// round 3
// speedup vs baseline: 1.2544x; 1.2544x over previous
#include <cuda_runtime.h>
#include <math.h>
#include <stdint.h>

#define NC 200000
#define NF 64
#define NH 128
#define NS 512

// ---- scratch ----
__device__ float    d_logits[NC];
__device__ float    d_e[NC];
__device__ float    d_w2k[NH];
__device__ float    d_c2;
__device__ unsigned d_gmax_u;
__device__ int      d_pcount;
__device__ int      d_pidx[NC];
__device__ float    d_pval[NC];
__device__ float    d_sums[NS];
__device__ float    d_sl[NS];
__device__ int      d_cnt[NS];

// float<->uint order-preserving (for atomicMax on floats)
__device__ __forceinline__ unsigned ford(float f) {
    unsigned u = __float_as_uint(f);
    return (u & 0x80000000u) ? ~u : (u | 0x80000000u);
}
__device__ __forceinline__ float funord(unsigned u) {
    return __uint_as_float((u & 0x80000000u) ? (u ^ 0x80000000u) : ~u);
}

__device__ __forceinline__ uint32_t f2tf32(float v) {
    uint32_t u;
    asm("cvt.rna.tf32.f32 %0, %1;" : "=r"(u) : "f"(v));
    return u;
}

__device__ __forceinline__ void mma_tf32(float c[4], const uint32_t a[4],
                                         uint32_t b0, uint32_t b1) {
    asm volatile(
        "mma.sync.aligned.m16n8k8.row.col.f32.tf32.tf32.f32 "
        "{%0,%1,%2,%3}, {%4,%5,%6,%7}, {%8,%9}, {%0,%1,%2,%3};"
        : "+f"(c[0]), "+f"(c[1]), "+f"(c[2]), "+f"(c[3])
        : "r"(a[0]), "r"(a[1]), "r"(a[2]), "r"(a[3]), "r"(b0), "r"(b1));
}

__global__ void k_init() {
    int t = blockIdx.x * blockDim.x + threadIdx.x;
    if (t < NS) d_sums[t] = 0.f;
    if (t == 0) { d_gmax_u = 0u; d_pcount = 0; }
}

// ---- fold W2/key_w: w2k[h] = sum_j W2[h][j]*kw[j]; c2 = b2 . kw ----
__global__ void k_prep(const float* __restrict__ W2, const float* __restrict__ b2,
                       const float* __restrict__ kw) {
    __shared__ float kws[NH];
    __shared__ float red[4];
    int h = threadIdx.x;  // 128
    kws[h] = kw[h];
    __syncthreads();
    float s = 0.f;
#pragma unroll 8
    for (int j = 0; j < NH; j++) s += W2[h * NH + j] * kws[j];
    d_w2k[h] = s;
    float c = b2[h] * kws[h];
    for (int o = 16; o; o >>= 1) c += __shfl_xor_sync(0xffffffffu, c, o);
    if ((h & 31) == 0) red[h >> 5] = c;
    __syncthreads();
    if (h == 0) d_c2 = red[0] + red[1] + red[2] + red[3];
}

// ================== tf32 mma.sync MLP ==================
// Per CTA: 128 clauses x NH=128 hidden, K=NF=64.
// A = features [128 x 64] row-major in smem (stride 68 floats, conflict-free frags)
// B = W1 [64 x 128] (native layout) in smem (stride 136 floats, conflict-free frags)
#define FS 68
#define WS 136
#define OFF_FEAT 0
#define OFF_W1   (128 * FS * 4)
#define OFF_B1   (OFF_W1 + 64 * WS * 4)
#define OFF_WK   (OFF_B1 + 512)
#define SMEM_MLP (OFF_WK + 512)

__global__ void __launch_bounds__(128) k_mlp(const float* __restrict__ feat,
                                             const float* __restrict__ W1,
                                             const float* __restrict__ b1) {
    extern __shared__ char smem[];
    float* featS = (float*)(smem + OFF_FEAT);
    float* W1S   = (float*)(smem + OFF_W1);
    float* b1s   = (float*)(smem + OFF_B1);
    float* wks   = (float*)(smem + OFF_WK);

    int tid = threadIdx.x;
    int wid = tid >> 5, lane = tid & 31;
    int g = lane >> 2, q = lane & 3;  // group / thread-in-group
    int base = blockIdx.x * 128;

    // stage A tile (zero-fill OOB rows)
    for (int i = tid; i < 128 * 16; i += 128) {
        int row = i >> 4, f4 = i & 15;
        float4 v = make_float4(0.f, 0.f, 0.f, 0.f);
        int c = base + row;
        if (c < NC) v = *(const float4*)(feat + (size_t)c * NF + f4 * 4);
        *(float4*)(featS + row * FS + f4 * 4) = v;
    }
    // stage W1 tile
    for (int i = tid; i < 64 * 32; i += 128) {
        int row = i >> 5, f4 = i & 31;
        float4 v = *(const float4*)(W1 + row * NH + f4 * 4);
        *(float4*)(W1S + row * WS + f4 * 4) = v;
    }
    if (tid < NH) { b1s[tid] = b1[tid]; wks[tid] = d_w2k[tid]; }
    __syncthreads();

    // load A fragments once: a[mt][kt][4]
    uint32_t a[2][8][4];
#pragma unroll
    for (int mt = 0; mt < 2; mt++) {
        int r0 = wid * 32 + mt * 16 + g;
#pragma unroll
        for (int kt = 0; kt < 8; kt++) {
            int k0 = kt * 8;
            a[mt][kt][0] = f2tf32(featS[r0 * FS + k0 + q]);
            a[mt][kt][1] = f2tf32(featS[(r0 + 8) * FS + k0 + q]);
            a[mt][kt][2] = f2tf32(featS[r0 * FS + k0 + q + 4]);
            a[mt][kt][3] = f2tf32(featS[(r0 + 8) * FS + k0 + q + 4]);
        }
    }

    float acc[2][2] = {{0.f, 0.f}, {0.f, 0.f}};  // [mt][row-half]
#pragma unroll
    for (int nt = 0; nt < 16; nt++) {
        float c0[4] = {0.f, 0.f, 0.f, 0.f};
        float c1[4] = {0.f, 0.f, 0.f, 0.f};
#pragma unroll
        for (int kt = 0; kt < 8; kt++) {
            int kk = kt * 8;
            uint32_t b0 = f2tf32(W1S[(kk + q) * WS + nt * 8 + g]);
            uint32_t b1f = f2tf32(W1S[(kk + q + 4) * WS + nt * 8 + g]);
            mma_tf32(c0, a[0][kt], b0, b1f);
            mma_tf32(c1, a[1][kt], b0, b1f);
        }
        int col0 = nt * 8 + 2 * q, col1 = col0 + 1;
        float bb0 = b1s[col0], bb1 = b1s[col1];
        float wk0 = wks[col0], wk1 = wks[col1];
        acc[0][0] += fmaxf(c0[0] + bb0, 0.f) * wk0 + fmaxf(c0[1] + bb1, 0.f) * wk1;
        acc[0][1] += fmaxf(c0[2] + bb0, 0.f) * wk0 + fmaxf(c0[3] + bb1, 0.f) * wk1;
        acc[1][0] += fmaxf(c1[0] + bb0, 0.f) * wk0 + fmaxf(c1[1] + bb1, 0.f) * wk1;
        acc[1][1] += fmaxf(c1[2] + bb0, 0.f) * wk0 + fmaxf(c1[3] + bb1, 0.f) * wk1;
    }

    // reduce over the 4 lanes of each quad (they hold different columns)
    float c2v = d_c2;
#pragma unroll
    for (int mt = 0; mt < 2; mt++) {
#pragma unroll
        for (int rh = 0; rh < 2; rh++) {
            float v = acc[mt][rh];
            v += __shfl_xor_sync(0xffffffffu, v, 1);
            v += __shfl_xor_sync(0xffffffffu, v, 2);
            if (q == 0) {
                int c = base + wid * 32 + mt * 16 + rh * 8 + g;
                if (c < NC) d_logits[c] = v + c2v;
            }
        }
    }
}

// ---- global max ----
__global__ void k_max() {
    int t = blockIdx.x * blockDim.x + threadIdx.x;
    float m = -3.4e38f;
    for (int n = t; n < NC; n += gridDim.x * blockDim.x) m = fmaxf(m, d_logits[n]);
    for (int o = 16; o; o >>= 1) m = fmaxf(m, __shfl_xor_sync(0xffffffffu, m, o));
    if ((threadIdx.x & 31) == 0) atomicMax(&d_gmax_u, ford(m));
}

// ---- e[n] = exp(logit - gmax); compact proof ----
__global__ void k_exp(const int* __restrict__ proof) {
    float gmax = funord(d_gmax_u);
    int t = blockIdx.x * blockDim.x + threadIdx.x;
    for (int n = t; n < NC; n += gridDim.x * blockDim.x) {
        float l = d_logits[n];
        d_e[n] = expf(l - gmax);
        if (proof[n]) {
            int p = atomicAdd(&d_pcount, 1);
            d_pidx[p] = n;
            d_pval[p] = l;
        }
    }
}

// ---- denominator: warp-per-step over 2048-element smem chunk ----
#define CHUNK 2048
#define DTPB 256
__global__ void __launch_bounds__(DTPB) k_denom(const int* __restrict__ sel) {
    __shared__ float es[CHUNK];
    int tid = threadIdx.x;
    int w = tid >> 5, l = tid & 31;
    int base = blockIdx.x * CHUNK;
    for (int i = tid; i < CHUNK; i += DTPB) {
        int n = base + i;
        es[i] = (n < NC) ? d_e[n] : 0.f;
    }
    __syncthreads();

    bool fast = (base + CHUNK) <= NC;
    for (int si = 0; si < 8; si++) {
        int s = blockIdx.y * 64 + si * 8 + w;
        const int* mrow = sel + (size_t)s * NC + base;
        float acc = 0.f;
        if (fast) {
            const int4* m4 = (const int4*)mrow;
#pragma unroll
            for (int j = 0; j < 16; j++) {
                int p = j * 32 + l;
                int4 m = m4[p];
                float4 e4 = *(const float4*)&es[p * 4];
                if (m.x) acc += e4.x;
                if (m.y) acc += e4.y;
                if (m.z) acc += e4.z;
                if (m.w) acc += e4.w;
            }
        } else {
            for (int j = 0; j < 16; j++) {
                int e0 = j * 128 + l * 4;
#pragma unroll
                for (int p = 0; p < 4; p++) {
                    int n = base + e0 + p;
                    if (n < NC && mrow[e0 + p]) acc += es[e0 + p];
                }
            }
        }
        for (int o = 16; o; o >>= 1) acc += __shfl_xor_sync(0xffffffffu, acc, o);
        if (l == 0) atomicAdd(&d_sums[s], acc);
    }
}

// ---- numerator: per step, gather over compacted proof set ----
__global__ void k_numer(const int* __restrict__ sel) {
    int s = blockIdx.x;
    int tid = threadIdx.x;  // 256
    int P = d_pcount;
    float sl = 0.f;
    int cnt = 0;
    const int* srow = sel + (size_t)s * NC;
    for (int j = tid; j < P; j += 256) {
        int n = d_pidx[j];
        if (srow[n]) { sl += d_pval[j]; cnt++; }
    }
    for (int o = 16; o; o >>= 1) {
        sl += __shfl_xor_sync(0xffffffffu, sl, o);
        cnt += __shfl_xor_sync(0xffffffffu, cnt, o);
    }
    __shared__ float rs[8];
    __shared__ int rc[8];
    if ((tid & 31) == 0) { rs[tid >> 5] = sl; rc[tid >> 5] = cnt; }
    __syncthreads();
    if (tid == 0) {
        float ts = 0.f;
        int tc = 0;
#pragma unroll
        for (int wv = 0; wv < 8; wv++) { ts += rs[wv]; tc += rc[wv]; }
        d_sl[s] = ts;
        d_cnt[s] = tc;
    }
}

// ---- final loss ----
__global__ void k_final(float* out) {
    float gmax = funord(d_gmax_u);
    int t = threadIdx.x;  // 512
    float v = (gmax + logf(d_sums[t])) - d_sl[t] / (float)d_cnt[t];
    for (int o = 16; o; o >>= 1) v += __shfl_xor_sync(0xffffffffu, v, o);
    __shared__ float red[16];
    if ((t & 31) == 0) red[t >> 5] = v;
    __syncthreads();
    if (t == 0) {
        float tot = 0.f;
#pragma unroll
        for (int w = 0; w < 16; w++) tot += red[w];
        out[0] = tot / (float)NS;
    }
}

extern "C" void kernel_launch(void* const* d_in, const int* in_sizes, int n_in,
                              void* d_out, int out_size) {
    const float* feat = (const float*)d_in[0];
    const float* W1   = (const float*)d_in[1];
    const float* b1   = (const float*)d_in[2];
    const float* W2   = (const float*)d_in[3];
    const float* b2   = (const float*)d_in[4];
    const float* kw   = (const float*)d_in[5];
    const int*   sel  = (const int*)d_in[6];
    const int*   proof= (const int*)d_in[7];
    float* out = (float*)d_out;

    static int smem_set = 0;
    if (!smem_set) {
        cudaFuncSetAttribute(k_mlp, cudaFuncAttributeMaxDynamicSharedMemorySize, SMEM_MLP);
        smem_set = 1;
    }

    k_init<<<1, 512>>>();
    k_prep<<<1, 128>>>(W2, b2, kw);
    k_mlp<<<(NC + 127) / 128, 128, SMEM_MLP>>>(feat, W1, b1);
    k_max<<<200, 256>>>();
    k_exp<<<200, 256>>>(proof);
    dim3 dg((NC + CHUNK - 1) / CHUNK, NS / 64);
    k_denom<<<dg, DTPB>>>(sel);
    k_numer<<<NS, 256>>>(sel);
    k_final<<<1, NS>>>(out);
}